// round 8
// baseline (speedup 1.0000x reference)
#include <cuda_runtime.h>
#include <cstdint>

// ---------------------------------------------------------------------------
// NodePredictor: y[b,n,:] = x[b,n,:] @ W[n] + b[n], out = y reshaped [B, N*DOUT]
// B=2048, N=64, DIN=DOUT=512, fp32. sm_100 legacy path (no tcgen05 under this
// harness's compile target).
//
// R8: CTA 128x128, 128 threads (4 warps, 2x2), warptile 64x64, 2 CTAs/SM.
//  - 4:1 MMA:LDSM ratio (R7's smem win) AND dual-CTA barrier overlap (R6's
//    occupancy win). 128thr x 2 CTA = 256 regs/thread budget -> no spills.
//  - A rounded to tf32 during staging (LDG->cvt->STS); B pre-rounded (g_Wt).
// ---------------------------------------------------------------------------

static constexpr int B_DIM   = 2048;
static constexpr int N_NODES = 64;
static constexpr int DIN     = 512;
static constexpr int DOUT    = 512;
static constexpr int OUT_W   = N_NODES * DOUT;   // 32768

static constexpr int TILE_M  = 128;
static constexpr int TILE_N  = 128;
static constexpr int TILE_K  = 32;               // 32 tf32 = 128 B row
static constexpr int K_ITERS = DIN / TILE_K;     // 16
static constexpr int THREADS = 128;
static constexpr int STAGES  = 3;

static constexpr int A_BYTES = TILE_M * 128;     // 16 KB
static constexpr int B_BYTES = TILE_N * 128;     // 16 KB
static constexpr int STAGE_BYTES = A_BYTES + B_BYTES;             // 32 KB
static constexpr int SMEM_BIAS   = STAGES * STAGE_BYTES;          // 98304
static constexpr int SMEM_TOTAL  = SMEM_BIAS + TILE_N * 4;        // 98816

// 64 MB scratch: Wt[n][dout][din], tf32(RNA)-rounded fp32 bits
__device__ float g_Wt[(size_t)N_NODES * DOUT * DIN];

// ---------------------------------------------------------------------------
__device__ __forceinline__ uint32_t smem_u32(const void* p) {
    uint32_t a;
    asm("{ .reg .u64 t; cvta.to.shared.u64 t, %1; cvt.u32.u64 %0, t; }" : "=r"(a) : "l"(p));
    return a;
}
__device__ __forceinline__ uint32_t rna_tf32(float x) {
    uint32_t r;
    asm("cvt.rna.tf32.f32 %0, %1;" : "=r"(r) : "f"(x));
    return r;
}
__device__ __forceinline__ uint32_t sw128(uint32_t off) {
    return off ^ ((off >> 3) & 0x70u);
}
__device__ __forceinline__ void cp_async16(uint32_t smem_dst, const void* gmem_src) {
    asm volatile("cp.async.cg.shared.global [%0], [%1], 16;"
                 :: "r"(smem_dst), "l"(gmem_src) : "memory");
}
__device__ __forceinline__ void cp_commit() {
    asm volatile("cp.async.commit_group;" ::: "memory");
}
template <int N>
__device__ __forceinline__ void cp_wait() {
    asm volatile("cp.async.wait_group %0;" :: "n"(N) : "memory");
}
__device__ __forceinline__ void ldsm_x4(uint32_t* r, uint32_t addr) {
    asm volatile("ldmatrix.sync.aligned.m8n8.x4.shared.b16 {%0,%1,%2,%3}, [%4];"
                 : "=r"(r[0]), "=r"(r[1]), "=r"(r[2]), "=r"(r[3]) : "r"(addr));
}
__device__ __forceinline__ void mma_tf32(float* c, const uint32_t* a, uint32_t b0, uint32_t b1) {
    asm volatile(
        "mma.sync.aligned.m16n8k8.row.col.f32.tf32.tf32.f32 "
        "{%0,%1,%2,%3}, {%4,%5,%6,%7}, {%8,%9}, {%0,%1,%2,%3};"
        : "+f"(c[0]), "+f"(c[1]), "+f"(c[2]), "+f"(c[3])
        : "r"(a[0]), "r"(a[1]), "r"(a[2]), "r"(a[3]), "r"(b0), "r"(b1));
}
__device__ __forceinline__ void sts128(uint32_t addr, uint32_t r0, uint32_t r1,
                                       uint32_t r2, uint32_t r3) {
    asm volatile("st.shared.v4.b32 [%0], {%1, %2, %3, %4};"
                 :: "r"(addr), "r"(r0), "r"(r1), "r"(r2), "r"(r3) : "memory");
}

// ---------------------------------------------------------------------------
// Pre-pass: Wt[n][o][i] = rna_tf32(W[n][i][o])
// ---------------------------------------------------------------------------
__global__ void wt_transpose_kernel(const float* __restrict__ W) {
    __shared__ float tile[32][33];
    const int n  = blockIdx.z;
    const int i0 = blockIdx.x * 32;
    const int o0 = blockIdx.y * 32;
    const int tx = threadIdx.x, ty = threadIdx.y;   // 32 x 8

    const float* src = W + ((size_t)n * DIN + i0) * DOUT + o0;
#pragma unroll
    for (int r = 0; r < 32; r += 8)
        tile[ty + r][tx] = src[(size_t)(ty + r) * DOUT + tx];
    __syncthreads();

    float* dst = g_Wt + ((size_t)n * DOUT + o0) * DIN + i0;
#pragma unroll
    for (int r = 0; r < 32; r += 8)
        dst[(size_t)(ty + r) * DIN + tx] = __uint_as_float(rna_tf32(tile[tx][ty + r]));
}

// ---------------------------------------------------------------------------
// Main GEMM: CTA = [128M x 128N] tile of one node. 4 warps 2x2, warptile 64x64.
// ---------------------------------------------------------------------------
__global__ __launch_bounds__(THREADS, 2)
void node_gemm_kernel(const float* __restrict__ x, const float* __restrict__ bias,
                      float* __restrict__ out) {
    extern __shared__ char smem[];
    const uint32_t sbase = smem_u32(smem);
    const int tid  = threadIdx.x;
    const int wid  = tid >> 5;
    const int lane = tid & 31;

    // block decode: nt fastest (L2 reuse of A slab), then mt, then node
    const int bx = blockIdx.x;
    const int n  = bx >> 6;
    const int mt = (bx >> 2) & 15;
    const int nt = bx & 3;
    const int m_base = mt * TILE_M;
    const int o_base = nt * TILE_N;

    reinterpret_cast<float*>(smem + SMEM_BIAS)[tid] = bias[n * DOUT + o_base + tid];

    // ---- staging: thread t owns A row t and B row t (8 x 16B chunks each)
    const float* a_src = x + ((size_t)(m_base + tid) * N_NODES + n) * DIN;
    const float* b_src = g_Wt + ((size_t)(n * DOUT + o_base + tid)) * DIN;
    uint32_t st_dst[8];
#pragma unroll
    for (int j = 0; j < 8; ++j)
        st_dst[j] = sw128((uint32_t)tid * 128u + (uint32_t)j * 16u);

    auto issue_b = [&](int stage, int kc) {
        const uint32_t bs = sbase + stage * STAGE_BYTES + A_BYTES;
        const float* bp = b_src + kc * TILE_K;
#pragma unroll
        for (int j = 0; j < 8; ++j) cp_async16(bs + st_dst[j], bp + j * 4);
        cp_commit();
    };
    auto ldg_a = [&](float4* v, int kc) {
        const float4* ap = reinterpret_cast<const float4*>(a_src + kc * TILE_K);
#pragma unroll
        for (int j = 0; j < 8; ++j) v[j] = ap[j];
    };
    auto sts_a = [&](int stage, const float4* v) {
        const uint32_t as = sbase + stage * STAGE_BYTES;
#pragma unroll
        for (int j = 0; j < 8; ++j)
            sts128(as + st_dst[j], rna_tf32(v[j].x), rna_tf32(v[j].y),
                   rna_tf32(v[j].z), rna_tf32(v[j].w));
    };

    // ---- ldmatrix lane address components (2x2 warp grid, warptile 64x64)
    const int wm = wid >> 1;       // 0..1  (M)
    const int wn = wid & 1;        // 0..1  (N)
    const uint32_t a_row  = (uint32_t)(wm * 64 + (lane & 15));
    const uint32_t a_cadd = (uint32_t)(lane >> 4);
    const uint32_t b_row  = (uint32_t)(wn * 64 + ((lane >> 4) << 3) + (lane & 7));
    const uint32_t b_cadd = (uint32_t)((lane >> 3) & 1);

    float c[4][8][4];
#pragma unroll
    for (int i = 0; i < 4; ++i)
#pragma unroll
        for (int j = 0; j < 8; ++j)
#pragma unroll
            for (int k = 0; k < 4; ++k) c[i][j][k] = 0.0f;

    // pure ldsm+mma consumer: per ks 8 ldsm.x4 feed 32 MMAs
    auto compute = [&](int stage) {
        const uint32_t as = sbase + stage * STAGE_BYTES;
        const uint32_t bs = as + A_BYTES;
#pragma unroll
        for (int ks = 0; ks < 4; ++ks) {
            const uint32_t ac = 2 * ks + a_cadd;
            const uint32_t bc = 2 * ks + b_cadd;
            uint32_t a[4][4];
#pragma unroll
            for (int m = 0; m < 4; ++m)
                ldsm_x4(a[m], as + sw128((a_row + m * 16) * 128u + ac * 16u));
            uint32_t bq[16];
#pragma unroll
            for (int g = 0; g < 4; ++g)
                ldsm_x4(bq + 4 * g, bs + sw128((b_row + g * 16) * 128u + bc * 16u));
#pragma unroll
            for (int m = 0; m < 4; ++m)
#pragma unroll
                for (int q = 0; q < 8; ++q)
                    mma_tf32(c[m][q], a[m], bq[2 * q], bq[2 * q + 1]);
        }
    };

    // ---- prologue: fill stages 0 and 1
    {
        float4 v0[8];
        ldg_a(v0, 0);
        issue_b(0, 0);
        issue_b(1, 1);
        sts_a(0, v0);
        ldg_a(v0, 1);       // reuse regs
        sts_a(1, v0);
        cp_wait<0>();
        __syncthreads();
    }

    int s = 0;
    for (int kc = 0; kc < K_ITERS; ++kc) {
        const int s_issue = (s + 2 >= STAGES) ? s + 2 - STAGES : s + 2;

        float4 vpre[8];
        const bool pre = (kc + 2 < K_ITERS);
        if (pre) {
            issue_b(s_issue, kc + 2);   // async B for stage kc+2
            ldg_a(vpre, kc + 2);        // LDG A held in regs across compute
        }

        compute(s);

        if (pre) sts_a(s_issue, vpre);  // round + store A for stage kc+2

        if (kc + 1 < K_ITERS) {
            if (kc + 1 == K_ITERS - 1) cp_wait<0>(); else cp_wait<1>();
            __syncthreads();
        }
        s = (s + 1 == STAGES) ? 0 : s + 1;
    }

    // ---- epilogue: add bias, store (c0,c1)/(c2,c3) as float2
    const float* bsm = reinterpret_cast<const float*>(smem + SMEM_BIAS);
    const int r_top = m_base + wm * 64 + (lane >> 2);
    const int lc0   = wn * 64 + (lane & 3) * 2;
#pragma unroll
    for (int m = 0; m < 4; ++m) {
#pragma unroll
        for (int q = 0; q < 8; ++q) {
            const int lc = lc0 + q * 8;
            const float b0 = bsm[lc], b1 = bsm[lc + 1];
            float* d0 = out + (size_t)(r_top + m * 16) * OUT_W + n * DOUT + o_base + lc;
            float* d1 = d0 + 8 * OUT_W;
            float2 v0 = { c[m][q][0] + b0, c[m][q][1] + b1 };
            float2 v1 = { c[m][q][2] + b0, c[m][q][3] + b1 };
            *reinterpret_cast<float2*>(d0) = v0;
            *reinterpret_cast<float2*>(d1) = v1;
        }
    }
}

// ---------------------------------------------------------------------------
extern "C" void kernel_launch(void* const* d_in, const int* in_sizes, int n_in,
                              void* d_out, int out_size) {
    const float* x = (const float*)d_in[0];
    const float* W = (const float*)d_in[1];
    const float* b = (const float*)d_in[2];
    float* out = (float*)d_out;

    cudaFuncSetAttribute(node_gemm_kernel,
                         cudaFuncAttributeMaxDynamicSharedMemorySize, SMEM_TOTAL);

    wt_transpose_kernel<<<dim3(DIN / 32, DOUT / 32, N_NODES), dim3(32, 8)>>>(W);

    const int grid = N_NODES * (B_DIM / TILE_M) * (DOUT / TILE_N);  // 4096
    node_gemm_kernel<<<grid, THREADS, SMEM_TOTAL>>>(x, b, out);
}

// round 9
// speedup vs baseline: 1.3292x; 1.3292x over previous
#include <cuda_runtime.h>
#include <cstdint>

// ---------------------------------------------------------------------------
// NodePredictor: y[b,n,:] = x[b,n,:] @ W[n] + b[n], out = y reshaped [B, N*DOUT]
// B=2048, N=64, DIN=DOUT=512, fp32. sm_100 legacy path (no tcgen05 under this
// harness's compile target).
//
// R9 = R6 topology (best: CTA 128x128, 8 warps 2x4, warptile 64x32, 3 stages,
// 2 CTAs/SM) with the A staging path deleted:
//  - A is cp.async'd RAW (fp32). mma.tf32 truncates operands to tf32 (RZ,
//    toward zero). Mean relative truncation bias = 2^-11 * ln2 = 3.38e-4.
//  - Compensation: prepass stores W' = rna_tf32(W * 1.000338) -- the
//    multiplicative biases cancel in x*W products. Residual error ~1e-4.
//  - Removes 1GB of LDG + all cvt from the main kernel, frees ~32 regs.
// ---------------------------------------------------------------------------

static constexpr int B_DIM   = 2048;
static constexpr int N_NODES = 64;
static constexpr int DIN     = 512;
static constexpr int DOUT    = 512;
static constexpr int OUT_W   = N_NODES * DOUT;   // 32768

static constexpr int TILE_M  = 128;
static constexpr int TILE_N  = 128;
static constexpr int TILE_K  = 32;               // 32 words = 128 B row
static constexpr int K_ITERS = DIN / TILE_K;     // 16
static constexpr int THREADS = 256;
static constexpr int STAGES  = 3;

static constexpr int A_BYTES = TILE_M * 128;     // 16 KB
static constexpr int STAGE_BYTES = 32768;        // A 16KB + B 16KB
static constexpr int SMEM_BIAS   = STAGES * STAGE_BYTES;          // 98304
static constexpr int SMEM_TOTAL  = SMEM_BIAS + TILE_N * 4;        // 98816

// tf32 truncation-bias compensation folded into W (see header comment)
static constexpr float W_COMP = 1.000338f;

// 64 MB scratch: Wt[n][dout][din], compensated + tf32(RNA)-rounded fp32 bits
__device__ float g_Wt[(size_t)N_NODES * DOUT * DIN];

// ---------------------------------------------------------------------------
__device__ __forceinline__ uint32_t smem_u32(const void* p) {
    uint32_t a;
    asm("{ .reg .u64 t; cvta.to.shared.u64 t, %1; cvt.u32.u64 %0, t; }" : "=r"(a) : "l"(p));
    return a;
}
__device__ __forceinline__ uint32_t rna_tf32(float x) {
    uint32_t r;
    asm("cvt.rna.tf32.f32 %0, %1;" : "=r"(r) : "f"(x));
    return r;
}
__device__ __forceinline__ uint32_t sw128(uint32_t off) {
    return off ^ ((off >> 3) & 0x70u);
}
__device__ __forceinline__ void cp_async16(uint32_t smem_dst, const void* gmem_src) {
    asm volatile("cp.async.cg.shared.global [%0], [%1], 16;"
                 :: "r"(smem_dst), "l"(gmem_src) : "memory");
}
__device__ __forceinline__ void cp_commit() {
    asm volatile("cp.async.commit_group;" ::: "memory");
}
template <int N>
__device__ __forceinline__ void cp_wait() {
    asm volatile("cp.async.wait_group %0;" :: "n"(N) : "memory");
}
__device__ __forceinline__ void ldsm_x4(uint32_t* r, uint32_t addr) {
    asm volatile("ldmatrix.sync.aligned.m8n8.x4.shared.b16 {%0,%1,%2,%3}, [%4];"
                 : "=r"(r[0]), "=r"(r[1]), "=r"(r[2]), "=r"(r[3]) : "r"(addr));
}
__device__ __forceinline__ void mma_tf32(float* c, const uint32_t* a, uint32_t b0, uint32_t b1) {
    asm volatile(
        "mma.sync.aligned.m16n8k8.row.col.f32.tf32.tf32.f32 "
        "{%0,%1,%2,%3}, {%4,%5,%6,%7}, {%8,%9}, {%0,%1,%2,%3};"
        : "+f"(c[0]), "+f"(c[1]), "+f"(c[2]), "+f"(c[3])
        : "r"(a[0]), "r"(a[1]), "r"(a[2]), "r"(a[3]), "r"(b0), "r"(b1));
}

// ---------------------------------------------------------------------------
// Pre-pass: Wt[n][o][i] = rna_tf32(W[n][i][o] * W_COMP)
// ---------------------------------------------------------------------------
__global__ void wt_transpose_kernel(const float* __restrict__ W) {
    __shared__ float tile[32][33];
    const int n  = blockIdx.z;
    const int i0 = blockIdx.x * 32;
    const int o0 = blockIdx.y * 32;
    const int tx = threadIdx.x, ty = threadIdx.y;   // 32 x 8

    const float* src = W + ((size_t)n * DIN + i0) * DOUT + o0;
#pragma unroll
    for (int r = 0; r < 32; r += 8)
        tile[ty + r][tx] = src[(size_t)(ty + r) * DOUT + tx];
    __syncthreads();

    float* dst = g_Wt + ((size_t)n * DOUT + o0) * DIN + i0;
#pragma unroll
    for (int r = 0; r < 32; r += 8)
        dst[(size_t)(ty + r) * DIN + tx] =
            __uint_as_float(rna_tf32(tile[tx][ty + r] * W_COMP));
}

// ---------------------------------------------------------------------------
// Main GEMM: CTA = [128M x 128N] tile of one node. 8 warps 2x4, warptile 64x32.
// ---------------------------------------------------------------------------
__global__ __launch_bounds__(THREADS, 2)
void node_gemm_kernel(const float* __restrict__ x, const float* __restrict__ bias,
                      float* __restrict__ out) {
    extern __shared__ char smem[];
    const uint32_t sbase = smem_u32(smem);
    const int tid  = threadIdx.x;
    const int wid  = tid >> 5;
    const int lane = tid & 31;

    // block decode: nt fastest (L2 reuse of A slab), then mt, then node
    const int bx = blockIdx.x;
    const int n  = bx >> 6;
    const int mt = (bx >> 2) & 15;
    const int nt = bx & 3;
    const int m_base = mt * TILE_M;
    const int o_base = nt * TILE_N;

    if (tid < TILE_N)
        reinterpret_cast<float*>(smem + SMEM_BIAS)[tid] = bias[n * DOUT + o_base + tid];

    // ---- staging: thread t -> row t/2, 16B-chunks (t&1)*4..+3, for A and B
    const int st_row = tid >> 1;
    const int st_cb  = (tid & 1) * 4;
    const float* a_src = x + ((size_t)(m_base + st_row) * N_NODES + n) * DIN + st_cb * 4;
    const float* b_src = g_Wt + ((size_t)(n * DOUT + o_base + st_row)) * DIN + st_cb * 4;
    uint32_t st_dst[4];
#pragma unroll
    for (int j = 0; j < 4; ++j)
        st_dst[j] = sw128((uint32_t)st_row * 128u + (uint32_t)(st_cb + j) * 16u);

    // one commit group per stage: 4x16B of A (raw fp32) + 4x16B of B
    auto issue = [&](int stage, int kc) {
        const uint32_t as = sbase + stage * STAGE_BYTES;
        const uint32_t bs = as + A_BYTES;
        const float* ap = a_src + kc * TILE_K;
        const float* bp = b_src + kc * TILE_K;
#pragma unroll
        for (int j = 0; j < 4; ++j) cp_async16(as + st_dst[j], ap + j * 4);
#pragma unroll
        for (int j = 0; j < 4; ++j) cp_async16(bs + st_dst[j], bp + j * 4);
        cp_commit();
    };

    // ---- ldmatrix lane address components (2x4 warp grid, warptile 64x32)
    const int wm = wid >> 2;       // 0..1  (M)
    const int wn = wid & 3;        // 0..3  (N)
    const uint32_t a_row  = (uint32_t)(wm * 64 + (lane & 15));
    const uint32_t a_cadd = (uint32_t)(lane >> 4);
    const uint32_t b_row  = (uint32_t)(wn * 32 + ((lane >> 4) << 3) + (lane & 7));
    const uint32_t b_cadd = (uint32_t)((lane >> 3) & 1);

    float c[4][4][4];
#pragma unroll
    for (int i = 0; i < 4; ++i)
#pragma unroll
        for (int j = 0; j < 4; ++j)
#pragma unroll
            for (int k = 0; k < 4; ++k) c[i][j][k] = 0.0f;

    // pure ldsm+mma consumer (A truncated to tf32 by the MMA itself)
    auto compute = [&](int stage) {
        const uint32_t as = sbase + stage * STAGE_BYTES;
        const uint32_t bs = as + A_BYTES;
#pragma unroll
        for (int ks = 0; ks < 4; ++ks) {
            const uint32_t ac = 2 * ks + a_cadd;
            const uint32_t bc = 2 * ks + b_cadd;
            uint32_t a[4][4];
#pragma unroll
            for (int m = 0; m < 4; ++m)
                ldsm_x4(a[m], as + sw128((a_row + m * 16) * 128u + ac * 16u));
            uint32_t bq[8];
            ldsm_x4(bq + 0, bs + sw128((b_row +  0) * 128u + bc * 16u));
            ldsm_x4(bq + 4, bs + sw128((b_row + 16) * 128u + bc * 16u));
#pragma unroll
            for (int m = 0; m < 4; ++m)
#pragma unroll
                for (int q = 0; q < 4; ++q)
                    mma_tf32(c[m][q], a[m], bq[2 * q], bq[2 * q + 1]);
        }
    };

    // ---- prologue: fill stages 0 and 1
    issue(0, 0);
    issue(1, 1);
    cp_wait<1>();
    __syncthreads();

    int s = 0;
    for (int kc = 0; kc < K_ITERS; ++kc) {
        const int s_issue = (s + 2 >= STAGES) ? s + 2 - STAGES : s + 2;

        if (kc + 2 < K_ITERS) issue(s_issue, kc + 2);

        compute(s);

        if (kc + 1 < K_ITERS) {
            if (kc + 2 < K_ITERS) cp_wait<1>(); else cp_wait<0>();
            __syncthreads();
        }
        s = (s + 1 == STAGES) ? 0 : s + 1;
    }

    // ---- epilogue: add bias, store (c0,c1)/(c2,c3) as float2
    const float* bsm = reinterpret_cast<const float*>(smem + SMEM_BIAS);
    const int r_top = m_base + wm * 64 + (lane >> 2);
    const int lc0   = wn * 32 + (lane & 3) * 2;
#pragma unroll
    for (int m = 0; m < 4; ++m) {
#pragma unroll
        for (int q = 0; q < 4; ++q) {
            const int lc = lc0 + q * 8;
            const float b0 = bsm[lc], b1 = bsm[lc + 1];
            float* d0 = out + (size_t)(r_top + m * 16) * OUT_W + n * DOUT + o_base + lc;
            float* d1 = d0 + 8 * OUT_W;
            float2 v0 = { c[m][q][0] + b0, c[m][q][1] + b1 };
            float2 v1 = { c[m][q][2] + b0, c[m][q][3] + b1 };
            *reinterpret_cast<float2*>(d0) = v0;
            *reinterpret_cast<float2*>(d1) = v1;
        }
    }
}

// ---------------------------------------------------------------------------
extern "C" void kernel_launch(void* const* d_in, const int* in_sizes, int n_in,
                              void* d_out, int out_size) {
    const float* x = (const float*)d_in[0];
    const float* W = (const float*)d_in[1];
    const float* b = (const float*)d_in[2];
    float* out = (float*)d_out;

    cudaFuncSetAttribute(node_gemm_kernel,
                         cudaFuncAttributeMaxDynamicSharedMemorySize, SMEM_TOTAL);

    wt_transpose_kernel<<<dim3(DIN / 32, DOUT / 32, N_NODES), dim3(32, 8)>>>(W);

    const int grid = N_NODES * (B_DIM / TILE_M) * (DOUT / TILE_N);  // 4096
    node_gemm_kernel<<<grid, THREADS, SMEM_TOTAL>>>(x, b, out);
}

// round 10
// speedup vs baseline: 1.3972x; 1.0512x over previous
#include <cuda_runtime.h>
#include <cstdint>

// ---------------------------------------------------------------------------
// NodePredictor: y[b,n,:] = x[b,n,:] @ W[n] + b[n], out = y reshaped [B, N*DOUT]
// B=2048, N=64, DIN=DOUT=512, fp32. sm_100 legacy path.
//
// R10 = R9 (cp.async raw A + W*1.000338 tf32 compensation, CTA 128x128,
// 8 warps 2x4, warptile 64x32, 3 stages, 2 CTAs/SM) + stall attacks:
//  - per-warp ks rotation (deconvoys post-barrier ldsm/mma phases)
//  - cp.async issue staggered into compute (off the post-barrier mio burst)
//  - 2 tiles per CTA (nt pair): next tile's stage fill overlaps epilogue STGs,
//    A slab L2-hot for tile 1. Grid 2048.
// ---------------------------------------------------------------------------

static constexpr int B_DIM   = 2048;
static constexpr int N_NODES = 64;
static constexpr int DIN     = 512;
static constexpr int DOUT    = 512;
static constexpr int OUT_W   = N_NODES * DOUT;   // 32768

static constexpr int TILE_M  = 128;
static constexpr int TILE_N  = 128;
static constexpr int TILE_K  = 32;               // 32 words = 128 B row
static constexpr int K_ITERS = DIN / TILE_K;     // 16
static constexpr int THREADS = 256;
static constexpr int STAGES  = 3;

static constexpr int A_BYTES = TILE_M * 128;     // 16 KB
static constexpr int STAGE_BYTES = 32768;        // A 16KB + B 16KB
static constexpr int SMEM_BIAS   = STAGES * STAGE_BYTES;          // 98304
static constexpr int SMEM_TOTAL  = SMEM_BIAS + 2 * TILE_N * 4;    // 99328

// tf32 truncation-bias compensation folded into W:
// mma.tf32 truncates A (RZ); mean rel bias 2^-11*ln2 = 3.38e-4, cancelled by
// scaling W by 1.000338 in the prepass (validated: rel_err 3.08e-4).
static constexpr float W_COMP = 1.000338f;

// 64 MB scratch: Wt[n][dout][din], compensated + tf32(RNA)-rounded fp32 bits
__device__ float g_Wt[(size_t)N_NODES * DOUT * DIN];

// ---------------------------------------------------------------------------
__device__ __forceinline__ uint32_t smem_u32(const void* p) {
    uint32_t a;
    asm("{ .reg .u64 t; cvta.to.shared.u64 t, %1; cvt.u32.u64 %0, t; }" : "=r"(a) : "l"(p));
    return a;
}
__device__ __forceinline__ uint32_t rna_tf32(float x) {
    uint32_t r;
    asm("cvt.rna.tf32.f32 %0, %1;" : "=r"(r) : "f"(x));
    return r;
}
__device__ __forceinline__ uint32_t sw128(uint32_t off) {
    return off ^ ((off >> 3) & 0x70u);
}
__device__ __forceinline__ void cp_async16(uint32_t smem_dst, const void* gmem_src) {
    asm volatile("cp.async.cg.shared.global [%0], [%1], 16;"
                 :: "r"(smem_dst), "l"(gmem_src) : "memory");
}
__device__ __forceinline__ void cp_commit() {
    asm volatile("cp.async.commit_group;" ::: "memory");
}
template <int N>
__device__ __forceinline__ void cp_wait() {
    asm volatile("cp.async.wait_group %0;" :: "n"(N) : "memory");
}
__device__ __forceinline__ void ldsm_x4(uint32_t* r, uint32_t addr) {
    asm volatile("ldmatrix.sync.aligned.m8n8.x4.shared.b16 {%0,%1,%2,%3}, [%4];"
                 : "=r"(r[0]), "=r"(r[1]), "=r"(r[2]), "=r"(r[3]) : "r"(addr));
}
__device__ __forceinline__ void mma_tf32(float* c, const uint32_t* a, uint32_t b0, uint32_t b1) {
    asm volatile(
        "mma.sync.aligned.m16n8k8.row.col.f32.tf32.tf32.f32 "
        "{%0,%1,%2,%3}, {%4,%5,%6,%7}, {%8,%9}, {%0,%1,%2,%3};"
        : "+f"(c[0]), "+f"(c[1]), "+f"(c[2]), "+f"(c[3])
        : "r"(a[0]), "r"(a[1]), "r"(a[2]), "r"(a[3]), "r"(b0), "r"(b1));
}

// ---------------------------------------------------------------------------
// Pre-pass: Wt[n][o][i] = rna_tf32(W[n][i][o] * W_COMP)
// ---------------------------------------------------------------------------
__global__ void wt_transpose_kernel(const float* __restrict__ W) {
    __shared__ float tile[32][33];
    const int n  = blockIdx.z;
    const int i0 = blockIdx.x * 32;
    const int o0 = blockIdx.y * 32;
    const int tx = threadIdx.x, ty = threadIdx.y;   // 32 x 8

    const float* src = W + ((size_t)n * DIN + i0) * DOUT + o0;
#pragma unroll
    for (int r = 0; r < 32; r += 8)
        tile[ty + r][tx] = src[(size_t)(ty + r) * DOUT + tx];
    __syncthreads();

    float* dst = g_Wt + ((size_t)n * DOUT + o0) * DIN + i0;
#pragma unroll
    for (int r = 0; r < 32; r += 8)
        dst[(size_t)(ty + r) * DIN + tx] =
            __uint_as_float(rna_tf32(tile[tx][ty + r] * W_COMP));
}

// ---------------------------------------------------------------------------
// Main GEMM: CTA handles TWO [128M x 128N] tiles (same node+mt, nt pair).
// ---------------------------------------------------------------------------
__global__ __launch_bounds__(THREADS, 2)
void node_gemm_kernel(const float* __restrict__ x, const float* __restrict__ bias,
                      float* __restrict__ out) {
    extern __shared__ char smem[];
    const uint32_t sbase = smem_u32(smem);
    const int tid  = threadIdx.x;
    const int wid  = tid >> 5;
    const int lane = tid & 31;

    // block decode: ntp fastest, then mt, then node
    const int bx  = blockIdx.x;
    const int n   = bx >> 5;
    const int mt  = (bx >> 1) & 15;
    const int ntp = bx & 1;                 // nt pair: tiles ntp*2, ntp*2+1
    const int m_base  = mt * TILE_M;
    const int o_base0 = (ntp * 2) * TILE_N;

    // both tiles' biases -> smem
    {
        const int t = tid >> 7;             // 0 or 1
        const int c = tid & 127;
        reinterpret_cast<float*>(smem + SMEM_BIAS)[t * TILE_N + c] =
            bias[n * DOUT + o_base0 + t * TILE_N + c];
    }

    // ---- staging: thread t -> row t/2, 16B-chunks (t&1)*4..+3, for A and B
    const int st_row = tid >> 1;
    const int st_cb  = (tid & 1) * 4;
    const float* a_src = x + ((size_t)(m_base + st_row) * N_NODES + n) * DIN + st_cb * 4;
    const float* b_src0 = g_Wt + ((size_t)(n * DOUT + o_base0 + st_row)) * DIN + st_cb * 4;
    uint32_t st_dst[4];
#pragma unroll
    for (int j = 0; j < 4; ++j)
        st_dst[j] = sw128((uint32_t)st_row * 128u + (uint32_t)(st_cb + j) * 16u);

    // one commit group per stage: 4x16B A (raw fp32) + 4x16B B (pre-rounded)
    auto issue = [&](int stage, int kc, const float* b_src) {
        const uint32_t as = sbase + stage * STAGE_BYTES;
        const uint32_t bs = as + A_BYTES;
        const float* ap = a_src + kc * TILE_K;
        const float* bp = b_src + kc * TILE_K;
#pragma unroll
        for (int j = 0; j < 4; ++j) cp_async16(as + st_dst[j], ap + j * 4);
#pragma unroll
        for (int j = 0; j < 4; ++j) cp_async16(bs + st_dst[j], bp + j * 4);
        cp_commit();
    };

    // ---- ldmatrix lane address components (2x4 warp grid, warptile 64x32)
    const int wm   = wid >> 2;     // 0..1  (M)
    const int wn   = wid & 3;      // 0..3  (N)
    const int wrot = wid & 3;      // per-warp ks rotation (deconvoy)
    const uint32_t a_row  = (uint32_t)(wm * 64 + (lane & 15));
    const uint32_t a_cadd = (uint32_t)(lane >> 4);
    const uint32_t b_row  = (uint32_t)(wn * 32 + ((lane >> 4) << 3) + (lane & 7));
    const uint32_t b_cadd = (uint32_t)((lane >> 3) & 1);

    float c[4][4][4];

    // one ks slice: 6 ldsm.x4 feeding 16 MMAs
    auto do_ks = [&](uint32_t as, uint32_t bs, int ks) {
        const uint32_t ac = 2 * (uint32_t)ks + a_cadd;
        const uint32_t bc = 2 * (uint32_t)ks + b_cadd;
        uint32_t a[4][4];
#pragma unroll
        for (int m = 0; m < 4; ++m)
            ldsm_x4(a[m], as + sw128((a_row + m * 16) * 128u + ac * 16u));
        uint32_t bq[8];
        ldsm_x4(bq + 0, bs + sw128((b_row +  0) * 128u + bc * 16u));
        ldsm_x4(bq + 4, bs + sw128((b_row + 16) * 128u + bc * 16u));
#pragma unroll
        for (int m = 0; m < 4; ++m)
#pragma unroll
            for (int q = 0; q < 4; ++q)
                mma_tf32(c[m][q], a[m], bq[2 * q], bq[2 * q + 1]);
    };

    // =======================================================================
    for (int t = 0; t < 2; ++t) {
        const int o_base = o_base0 + t * TILE_N;
        const float* b_srcT = b_src0 + (size_t)t * TILE_N * DIN;

#pragma unroll
        for (int i = 0; i < 4; ++i)
#pragma unroll
            for (int j = 0; j < 4; ++j)
#pragma unroll
                for (int k = 0; k < 4; ++k) c[i][j][k] = 0.0f;

        if (t == 0) {
            // cold prologue: fill stages 0 and 1
            issue(0, 0, b_srcT);
            issue(1, 1, b_srcT);
            cp_wait<1>();
            __syncthreads();
        }
        // (t == 1: stages 0,1 were filled during tile 0's epilogue)

        int s = 0;
        for (int kc = 0; kc < K_ITERS; ++kc) {
            const int s_issue = (s + 2 >= STAGES) ? s + 2 - STAGES : s + 2;
            const uint32_t as = sbase + s * STAGE_BYTES;
            const uint32_t bs = as + A_BYTES;
            const bool pre = (kc + 2 < K_ITERS);

            // ks order rotated per warp; staging issued after the first slice
            do_ks(as, bs, (0 + wrot) & 3);
            if (pre) issue(s_issue, kc + 2, b_srcT);
            do_ks(as, bs, (1 + wrot) & 3);
            do_ks(as, bs, (2 + wrot) & 3);
            do_ks(as, bs, (3 + wrot) & 3);

            if (kc + 1 < K_ITERS) {
                if (pre) cp_wait<1>(); else cp_wait<0>();
                __syncthreads();
            }
            s = (s + 1 == STAGES) ? 0 : s + 1;
        }

        // publish stage buffers as free before refilling for the next tile
        __syncthreads();

        if (t == 0) {
            // fill next tile's stages 0,1 NOW -> overlaps the epilogue STGs
            const float* b_srcN = b_src0 + (size_t)TILE_N * DIN;
            issue(0, 0, b_srcN);
            issue(1, 1, b_srcN);
        }

        // ---- epilogue: add bias, store (c0,c1)/(c2,c3) as float2
        const float* bsm = reinterpret_cast<const float*>(smem + SMEM_BIAS) + t * TILE_N;
        const int r_top = m_base + wm * 64 + (lane >> 2);
        const int lc0   = wn * 32 + (lane & 3) * 2;
#pragma unroll
        for (int m = 0; m < 4; ++m) {
#pragma unroll
            for (int q = 0; q < 4; ++q) {
                const int lc = lc0 + q * 8;
                const float b0 = bsm[lc], b1 = bsm[lc + 1];
                float* d0 = out + (size_t)(r_top + m * 16) * OUT_W + n * DOUT + o_base + lc;
                float* d1 = d0 + 8 * OUT_W;
                float2 v0 = { c[m][q][0] + b0, c[m][q][1] + b1 };
                float2 v1 = { c[m][q][2] + b0, c[m][q][3] + b1 };
                *reinterpret_cast<float2*>(d0) = v0;
                *reinterpret_cast<float2*>(d1) = v1;
            }
        }

        if (t == 0) {
            cp_wait<0>();       // next tile's stages 0,1 landed
            __syncthreads();
        }
    }
}

// ---------------------------------------------------------------------------
extern "C" void kernel_launch(void* const* d_in, const int* in_sizes, int n_in,
                              void* d_out, int out_size) {
    const float* x = (const float*)d_in[0];
    const float* W = (const float*)d_in[1];
    const float* b = (const float*)d_in[2];
    float* out = (float*)d_out;

    cudaFuncSetAttribute(node_gemm_kernel,
                         cudaFuncAttributeMaxDynamicSharedMemorySize, SMEM_TOTAL);

    wt_transpose_kernel<<<dim3(DIN / 32, DOUT / 32, N_NODES), dim3(32, 8)>>>(W);

    const int grid = N_NODES * (B_DIM / TILE_M) * 2;   // 64*16*2 = 2048
    node_gemm_kernel<<<grid, THREADS, SMEM_TOTAL>>>(x, b, out);
}

// round 11
// speedup vs baseline: 1.9903x; 1.4245x over previous
#include <cuda_runtime.h>
#include <cuda_fp16.h>
#include <cstdint>

// ---------------------------------------------------------------------------
// NodePredictor: y[b,n,:] = x[b,n,:] @ W[n] + b[n], out = y reshaped [B, N*DOUT]
// B=2048, N=64, DIN=DOUT=512, fp32. sm_100 legacy path.
//
// R11: fp16 MMA (m16n8k16.f32.f16.f16.f32) — tf32 tensor% has been pinned at
// ~50% across all configs => tf32 runs at half the fp16 pipe rate; halve the
// tensor cycles by moving operands to fp16 (RNE, unbiased; predicted rel_err
// ~4-5e-4). Both operands pre-converted by prepasses so the GEMM keeps the
// validated pure-cp.async R10 structure (2 tiles/CTA, ks rotation, 3 stages).
// ---------------------------------------------------------------------------

static constexpr int B_DIM   = 2048;
static constexpr int N_NODES = 64;
static constexpr int DIN     = 512;
static constexpr int DOUT    = 512;
static constexpr int OUT_W   = N_NODES * DOUT;   // 32768

static constexpr int TILE_M  = 128;
static constexpr int TILE_N  = 128;
static constexpr int TILE_K  = 64;               // 64 halfs = 128 B row
static constexpr int K_ITERS = DIN / TILE_K;     // 8
static constexpr int THREADS = 256;
static constexpr int STAGES  = 3;

static constexpr int A_BYTES = TILE_M * 128;     // 16 KB
static constexpr int STAGE_BYTES = 32768;        // A 16KB + B 16KB
static constexpr int SMEM_BIAS   = STAGES * STAGE_BYTES;          // 98304
static constexpr int SMEM_TOTAL  = SMEM_BIAS + 2 * TILE_N * 4;    // 99328

// scratch: x and W^T pre-converted to fp16 (RNE)
__device__ __half g_Xh[(size_t)B_DIM * N_NODES * DIN];            // 128 MB
__device__ __half g_Wh[(size_t)N_NODES * DOUT * DIN];             // 32 MB

// ---------------------------------------------------------------------------
__device__ __forceinline__ uint32_t smem_u32(const void* p) {
    uint32_t a;
    asm("{ .reg .u64 t; cvta.to.shared.u64 t, %1; cvt.u32.u64 %0, t; }" : "=r"(a) : "l"(p));
    return a;
}
__device__ __forceinline__ uint32_t sw128(uint32_t off) {
    return off ^ ((off >> 3) & 0x70u);
}
__device__ __forceinline__ void cp_async16(uint32_t smem_dst, const void* gmem_src) {
    asm volatile("cp.async.cg.shared.global [%0], [%1], 16;"
                 :: "r"(smem_dst), "l"(gmem_src) : "memory");
}
__device__ __forceinline__ void cp_commit() {
    asm volatile("cp.async.commit_group;" ::: "memory");
}
template <int N>
__device__ __forceinline__ void cp_wait() {
    asm volatile("cp.async.wait_group %0;" :: "n"(N) : "memory");
}
__device__ __forceinline__ void ldsm_x4(uint32_t* r, uint32_t addr) {
    asm volatile("ldmatrix.sync.aligned.m8n8.x4.shared.b16 {%0,%1,%2,%3}, [%4];"
                 : "=r"(r[0]), "=r"(r[1]), "=r"(r[2]), "=r"(r[3]) : "r"(addr));
}
__device__ __forceinline__ void mma_f16(float* c, const uint32_t* a, uint32_t b0, uint32_t b1) {
    asm volatile(
        "mma.sync.aligned.m16n8k16.row.col.f32.f16.f16.f32 "
        "{%0,%1,%2,%3}, {%4,%5,%6,%7}, {%8,%9}, {%0,%1,%2,%3};"
        : "+f"(c[0]), "+f"(c[1]), "+f"(c[2]), "+f"(c[3])
        : "r"(a[0]), "r"(a[1]), "r"(a[2]), "r"(a[3]), "r"(b0), "r"(b1));
}

// ---------------------------------------------------------------------------
// Pre-pass 1: g_Xh = half(x)  (RNE)
// ---------------------------------------------------------------------------
__global__ void x_convert_kernel(const float* __restrict__ x) {
    const size_t i = (size_t)blockIdx.x * blockDim.x + threadIdx.x;   // one float4
    const float4 v = reinterpret_cast<const float4*>(x)[i];
    __half2* dst = reinterpret_cast<__half2*>(g_Xh) + 2 * i;
    dst[0] = __floats2half2_rn(v.x, v.y);
    dst[1] = __floats2half2_rn(v.z, v.w);
}

// ---------------------------------------------------------------------------
// Pre-pass 2: g_Wh[n][o][i] = half(W[n][i][o])  (RNE)
// ---------------------------------------------------------------------------
__global__ void wt_transpose_kernel(const float* __restrict__ W) {
    __shared__ float tile[32][33];
    const int n  = blockIdx.z;
    const int i0 = blockIdx.x * 32;
    const int o0 = blockIdx.y * 32;
    const int tx = threadIdx.x, ty = threadIdx.y;   // 32 x 8

    const float* src = W + ((size_t)n * DIN + i0) * DOUT + o0;
#pragma unroll
    for (int r = 0; r < 32; r += 8)
        tile[ty + r][tx] = src[(size_t)(ty + r) * DOUT + tx];
    __syncthreads();

    __half* dst = g_Wh + ((size_t)n * DOUT + o0) * DIN + i0;
#pragma unroll
    for (int r = 0; r < 32; r += 8)
        dst[(size_t)(ty + r) * DIN + tx] = __float2half_rn(tile[tx][ty + r]);
}

// ---------------------------------------------------------------------------
// Main GEMM: CTA handles TWO [128M x 128N] tiles (same node+mt, nt pair).
// 8 warps 2x4, warptile 64x32, fp16 MMA m16n8k16.
// ---------------------------------------------------------------------------
__global__ __launch_bounds__(THREADS, 2)
void node_gemm_kernel(const float* __restrict__ bias, float* __restrict__ out) {
    extern __shared__ char smem[];
    const uint32_t sbase = smem_u32(smem);
    const int tid  = threadIdx.x;
    const int wid  = tid >> 5;
    const int lane = tid & 31;

    // block decode: ntp fastest, then mt, then node
    const int bx  = blockIdx.x;
    const int n   = bx >> 5;
    const int mt  = (bx >> 1) & 15;
    const int ntp = bx & 1;                 // nt pair: tiles ntp*2, ntp*2+1
    const int m_base  = mt * TILE_M;
    const int o_base0 = (ntp * 2) * TILE_N;

    // both tiles' biases -> smem
    {
        const int t = tid >> 7;             // 0 or 1
        const int c = tid & 127;
        reinterpret_cast<float*>(smem + SMEM_BIAS)[t * TILE_N + c] =
            bias[n * DOUT + o_base0 + t * TILE_N + c];
    }

    // ---- staging: thread t -> row t/2, 16B-chunks (t&1)*4..+3 (8 halfs each)
    const int st_row = tid >> 1;
    const int st_cb  = (tid & 1) * 4;
    const __half* a_src = g_Xh + ((size_t)(m_base + st_row) * N_NODES + n) * DIN + st_cb * 8;
    const __half* b_src0 = g_Wh + ((size_t)(n * DOUT + o_base0 + st_row)) * DIN + st_cb * 8;
    uint32_t st_dst[4];
#pragma unroll
    for (int j = 0; j < 4; ++j)
        st_dst[j] = sw128((uint32_t)st_row * 128u + (uint32_t)(st_cb + j) * 16u);

    // one commit group per stage: 4x16B A + 4x16B B (both fp16)
    auto issue = [&](int stage, int kc, const __half* b_src) {
        const uint32_t as = sbase + stage * STAGE_BYTES;
        const uint32_t bs = as + A_BYTES;
        const __half* ap = a_src + kc * TILE_K;
        const __half* bp = b_src + kc * TILE_K;
#pragma unroll
        for (int j = 0; j < 4; ++j) cp_async16(as + st_dst[j], ap + j * 8);
#pragma unroll
        for (int j = 0; j < 4; ++j) cp_async16(bs + st_dst[j], bp + j * 8);
        cp_commit();
    };

    // ---- ldmatrix lane address components (2x4 warp grid, warptile 64x32)
    // fp16 m16n8k16: 16B chunk = 8 halfs; one ks = 16 k = 2 chunks.
    const int wm   = wid >> 2;     // 0..1  (M)
    const int wn   = wid & 3;      // 0..3  (N)
    const int wrot = wid & 3;      // per-warp ks rotation (deconvoy)
    const uint32_t a_row  = (uint32_t)(wm * 64 + (lane & 15));
    const uint32_t a_cadd = (uint32_t)(lane >> 4);
    const uint32_t b_row  = (uint32_t)(wn * 32 + ((lane >> 4) << 3) + (lane & 7));
    const uint32_t b_cadd = (uint32_t)((lane >> 3) & 1);

    float c[4][4][4];

    // one ks slice (k16): 6 ldsm.x4 feeding 16 MMAs
    auto do_ks = [&](uint32_t as, uint32_t bs, int ks) {
        const uint32_t ac = 2 * (uint32_t)ks + a_cadd;
        const uint32_t bc = 2 * (uint32_t)ks + b_cadd;
        uint32_t a[4][4];
#pragma unroll
        for (int m = 0; m < 4; ++m)
            ldsm_x4(a[m], as + sw128((a_row + m * 16) * 128u + ac * 16u));
        uint32_t bq[8];
        ldsm_x4(bq + 0, bs + sw128((b_row +  0) * 128u + bc * 16u));
        ldsm_x4(bq + 4, bs + sw128((b_row + 16) * 128u + bc * 16u));
#pragma unroll
        for (int m = 0; m < 4; ++m)
#pragma unroll
            for (int q = 0; q < 4; ++q)
                mma_f16(c[m][q], a[m], bq[2 * q], bq[2 * q + 1]);
    };

    // =======================================================================
    for (int t = 0; t < 2; ++t) {
        const int o_base = o_base0 + t * TILE_N;
        const __half* b_srcT = b_src0 + (size_t)t * TILE_N * DIN;

#pragma unroll
        for (int i = 0; i < 4; ++i)
#pragma unroll
            for (int j = 0; j < 4; ++j)
#pragma unroll
                for (int k = 0; k < 4; ++k) c[i][j][k] = 0.0f;

        if (t == 0) {
            // cold prologue: fill stages 0 and 1
            issue(0, 0, b_srcT);
            issue(1, 1, b_srcT);
            cp_wait<1>();
            __syncthreads();
        }
        // (t == 1: stages 0,1 were filled during tile 0's epilogue)

        int s = 0;
        for (int kc = 0; kc < K_ITERS; ++kc) {
            const int s_issue = (s + 2 >= STAGES) ? s + 2 - STAGES : s + 2;
            const uint32_t as = sbase + s * STAGE_BYTES;
            const uint32_t bs = as + A_BYTES;
            const bool pre = (kc + 2 < K_ITERS);

            // ks order rotated per warp; staging issued after the first slice
            do_ks(as, bs, (0 + wrot) & 3);
            if (pre) issue(s_issue, kc + 2, b_srcT);
            do_ks(as, bs, (1 + wrot) & 3);
            do_ks(as, bs, (2 + wrot) & 3);
            do_ks(as, bs, (3 + wrot) & 3);

            if (kc + 1 < K_ITERS) {
                if (pre) cp_wait<1>(); else cp_wait<0>();
                __syncthreads();
            }
            s = (s + 1 == STAGES) ? 0 : s + 1;
        }

        // publish stage buffers as free before refilling for the next tile
        __syncthreads();

        if (t == 0) {
            // fill next tile's stages 0,1 NOW -> overlaps the epilogue STGs
            const __half* b_srcN = b_src0 + (size_t)TILE_N * DIN;
            issue(0, 0, b_srcN);
            issue(1, 1, b_srcN);
        }

        // ---- epilogue: add bias, store (c0,c1)/(c2,c3) as float2
        const float* bsm = reinterpret_cast<const float*>(smem + SMEM_BIAS) + t * TILE_N;
        const int r_top = m_base + wm * 64 + (lane >> 2);
        const int lc0   = wn * 32 + (lane & 3) * 2;
#pragma unroll
        for (int m = 0; m < 4; ++m) {
#pragma unroll
            for (int q = 0; q < 4; ++q) {
                const int lc = lc0 + q * 8;
                const float b0 = bsm[lc], b1 = bsm[lc + 1];
                float* d0 = out + (size_t)(r_top + m * 16) * OUT_W + n * DOUT + o_base + lc;
                float* d1 = d0 + 8 * OUT_W;
                float2 v0 = { c[m][q][0] + b0, c[m][q][1] + b1 };
                float2 v1 = { c[m][q][2] + b0, c[m][q][3] + b1 };
                *reinterpret_cast<float2*>(d0) = v0;
                *reinterpret_cast<float2*>(d1) = v1;
            }
        }

        if (t == 0) {
            cp_wait<0>();       // next tile's stages 0,1 landed
            __syncthreads();
        }
    }
}

// ---------------------------------------------------------------------------
extern "C" void kernel_launch(void* const* d_in, const int* in_sizes, int n_in,
                              void* d_out, int out_size) {
    const float* x = (const float*)d_in[0];
    const float* W = (const float*)d_in[1];
    const float* b = (const float*)d_in[2];
    float* out = (float*)d_out;

    cudaFuncSetAttribute(node_gemm_kernel,
                         cudaFuncAttributeMaxDynamicSharedMemorySize, SMEM_TOTAL);

    // prepasses: x -> fp16, W -> transposed fp16
    const size_t n_f4 = (size_t)B_DIM * N_NODES * DIN / 4;        // 16.8M float4
    x_convert_kernel<<<(unsigned)(n_f4 / 256), 256>>>(x);
    wt_transpose_kernel<<<dim3(DIN / 32, DOUT / 32, N_NODES), dim3(32, 8)>>>(W);

    const int grid = N_NODES * (B_DIM / TILE_M) * 2;   // 64*16*2 = 2048
    node_gemm_kernel<<<grid, THREADS, SMEM_TOTAL>>>(b, out);
}